// round 5
// baseline (speedup 1.0000x reference)
#include <cuda_runtime.h>
#include <math.h>

// Problem constants
#define B 64
#define C 256
#define H 56
#define W 56
#define HW (H * W)            // 3136
#define HW4 (HW / 4)          // 784 float4 per plane
#define R 16
#define PLANES (B * C)        // 16384
#define POSITION 205          // round(0.8 * 256)

// Pipeline shape
#define NBLOCKS 256           // <= 296 guaranteed-resident wave-1 blocks
#define NTHREADS 256          // 8 warps
#define WARPS_TOTAL (NBLOCKS * 8)      // 2048
#define NGROUPS 8
#define GROUP_PLANES (PLANES / NGROUPS)  // 2048 (= WARPS_TOTAL: 1 plane/warp/group)

#define SENT 0xFFFFFFFFu      // NaN bit pattern: unreachable as mean or 0/1 mask

// Scratch (allocation-free rule: __device__ globals). Sentinel-poisoned each launch.
__device__ unsigned g_y[PLANES];      // GAP mean (bits), SENT = not ready
__device__ unsigned g_mask[PLANES];   // 0x3F800000 / 0x0 (bits), SENT = not ready

// ---- spin-safe L2 load (volatile asm: cannot be hoisted, bypasses L1) ----
__device__ __forceinline__ unsigned ld_cg_spin(const unsigned* p) {
    unsigned v;
    asm volatile("ld.global.cg.u32 %0, [%1];" : "=r"(v) : "l"(p) : "memory");
    return v;
}
__device__ __forceinline__ void st_cg(unsigned* p, unsigned v) {
    asm volatile("st.global.cg.u32 [%0], %1;" :: "l"(p), "r"(v) : "memory");
}

// ---------------------------------------------------------------------------
// Reset kernel: re-poison sentinels (required per graph replay; determinism).
// ---------------------------------------------------------------------------
__global__ __launch_bounds__(256) void k_reset() {
    const int i = blockIdx.x * 256 + threadIdx.x;
    if (i < PLANES) { g_y[i] = SENT; g_mask[i] = SENT; }
}

// ---------------------------------------------------------------------------
// Warp-level MLP + sigmoid + exact stable-sort rank mask for one batch.
// Executed by the warp that GAP'd the batch's last channel. Lane L owns
// channels c = t*32 + L, t = 0..7.
// ---------------------------------------------------------------------------
__device__ __forceinline__ void mlp_mask_batch(int b,
                                               const float* __restrict__ W1,
                                               const float* __restrict__ W2,
                                               int lane) {
    // Gather y (spin per word until the producing warp stored it)
    float y[8];
    #pragma unroll
    for (int t = 0; t < 8; t++) {
        const unsigned* p = &g_y[b * C + t * 32 + lane];
        unsigned v = ld_cg_spin(p);
        while (v == SENT) { __nanosleep(64); v = ld_cg_spin(p); }
        y[t] = __uint_as_float(v);
    }

    // h[r] = relu(dot(y, W1[r,:])) — butterfly reduce so every lane holds h[r]
    float h[R];
    #pragma unroll
    for (int r = 0; r < R; r++) {
        const float* __restrict__ w = W1 + r * C;
        float a = 0.0f;
        #pragma unroll
        for (int t = 0; t < 8; t++) a = fmaf(y[t], w[t * 32 + lane], a);
        #pragma unroll
        for (int off = 16; off > 0; off >>= 1)
            a += __shfl_xor_sync(0xFFFFFFFFu, a, off);
        h[r] = fmaxf(a, 0.0f);
    }

    // s[c] = sigmoid(dot(h, W2[c,:]))
    float s[8];
    #pragma unroll
    for (int t = 0; t < 8; t++) {
        const float* __restrict__ w2 = W2 + (t * 32 + lane) * R;
        float a = 0.0f;
        #pragma unroll
        for (int r = 0; r < R; r++) a = fmaf(h[r], w2[r], a);
        s[t] = 1.0f / (1.0f + expf(-a));
    }

    // Exact stable ascending rank: rank(c) = #less + #equal-at-earlier-index.
    int less[8], eqb[8];
    #pragma unroll
    for (int t = 0; t < 8; t++) { less[t] = 0; eqb[t] = 0; }
    for (int j = 0; j < C; j++) {
        const float vj = __shfl_sync(0xFFFFFFFFu, s[j >> 5], j & 31);
        #pragma unroll
        for (int t = 0; t < 8; t++) {
            const int c = t * 32 + lane;
            less[t] += (vj < s[t]) ? 1 : 0;
            eqb[t]  += (vj == s[t] && j < c) ? 1 : 0;
        }
    }
    // Exactly one channel has rank POSITION-1 (ranks form a permutation).
    float cand = 0.0f;
    #pragma unroll
    for (int t = 0; t < 8; t++)
        if (less[t] + eqb[t] == POSITION - 1) cand = s[t];
    #pragma unroll
    for (int off = 16; off > 0; off >>= 1)
        cand = fmaxf(cand, __shfl_xor_sync(0xFFFFFFFFu, cand, off));

    // Publish masks (single-word self-synchronizing: no fence needed)
    #pragma unroll
    for (int t = 0; t < 8; t++) {
        const int c = t * 32 + lane;
        st_cg(&g_mask[b * C + c], (s[t] <= cand) ? 0x3F800000u : 0u);
    }
}

// ---------------------------------------------------------------------------
// Scale one plane: spin on its mask word, then copy/zero with streaming stores.
// ---------------------------------------------------------------------------
__device__ __forceinline__ void scale_plane(int plane,
                                            const float* __restrict__ x,
                                            float* __restrict__ out, int lane) {
    const unsigned* mp = &g_mask[plane];
    unsigned mv = ld_cg_spin(mp);
    while (mv == SENT) { __nanosleep(64); mv = ld_cg_spin(mp); }

    const size_t base = (size_t)plane * HW;
    float4* __restrict__ po = reinterpret_cast<float4*>(out + base);

    if (mv == 0u) {
        const float4 z = make_float4(0.f, 0.f, 0.f, 0.f);
        #pragma unroll 8
        for (int k = 0; k < 24; k++) __stcs(&po[k * 32 + lane], z);
        if (lane < 16) __stcs(&po[24 * 32 + lane], z);
    } else {
        const float4* __restrict__ px = reinterpret_cast<const float4*>(x + base);
        #pragma unroll 8
        for (int k = 0; k < 24; k++) __stcs(&po[k * 32 + lane], px[k * 32 + lane]);
        if (lane < 16) __stcs(&po[24 * 32 + lane], px[24 * 32 + lane]);
    }
}

// ---------------------------------------------------------------------------
// Fused pipelined kernel. Per warp, per group g:
//   GAP(plane of g)  ->  [if last channel of a batch: MLP+mask]  ->  scale(plane of g-1)
// Scale reads re-hit L2 (only ~75MB of allocations between read and re-read).
// ---------------------------------------------------------------------------
__global__ __launch_bounds__(NTHREADS, 2) void k_fused(const float* __restrict__ x,
                                                       const float* __restrict__ W1,
                                                       const float* __restrict__ W2,
                                                       float* __restrict__ out) {
    const int warp = threadIdx.x >> 5;
    const int lane = threadIdx.x & 31;
    const int wg = blockIdx.x * 8 + warp;   // 0..2047

    for (int g = 0; g < NGROUPS; g++) {
        // ---- GAP my plane of group g ----
        const int plane = g * GROUP_PLANES + wg;
        const float4* __restrict__ px =
            reinterpret_cast<const float4*>(x + (size_t)plane * HW);
        float acc = 0.0f;
        #pragma unroll 8
        for (int k = 0; k < 24; k++) {
            float4 v = px[k * 32 + lane];
            acc += (v.x + v.y) + (v.z + v.w);
        }
        if (lane < 16) {
            float4 v = px[24 * 32 + lane];
            acc += (v.x + v.y) + (v.z + v.w);
        }
        #pragma unroll
        for (int off = 16; off > 0; off >>= 1)
            acc += __shfl_down_sync(0xFFFFFFFFu, acc, off);
        if (lane == 0)
            st_cg(&g_y[plane], __float_as_uint(acc * (1.0f / (float)HW)));

        // ---- batch complete trigger (warp-uniform condition) ----
        if ((plane & (C - 1)) == C - 1)
            mlp_mask_batch(plane >> 8, W1, W2, lane);

        // ---- scale my plane of group g-1 (still L2-resident) ----
        if (g > 0)
            scale_plane((g - 1) * GROUP_PLANES + wg, x, out, lane);
    }
    scale_plane((NGROUPS - 1) * GROUP_PLANES + wg, x, out, lane);
}

// ---------------------------------------------------------------------------
extern "C" void kernel_launch(void* const* d_in, const int* in_sizes, int n_in,
                              void* d_out, int out_size) {
    const float* x  = (const float*)d_in[0];
    const float* W1 = (const float*)d_in[1];
    const float* W2 = (const float*)d_in[2];
    float* out = (float*)d_out;

    k_reset<<<(PLANES + 255) / 256, 256>>>();
    k_fused<<<NBLOCKS, NTHREADS>>>(x, W1, W2, out);
}